// round 5
// baseline (speedup 1.0000x reference)
#include <cuda_runtime.h>
#include <cstdint>

#define NN   1048576
#define NE   4194304
#define NB   2048
#define DIM  32
#define FXD  55
#define OUTD 128
#define SEQL 1000
#define EMBD 128
#define NFLT 32
#define KW   8
#define LCONV 121

typedef unsigned long long ull;

// ---------------- device scratch ----------------
__device__ float  g_A[(size_t)NN * DIM];       // aggregate accumulator
__device__ float  g_R[(size_t)NN * DIM];       // post-relu pre-BN features
__device__ double g_part[64 * 64];             // staged BN stats [slot][sum32|sumsq32]
__device__ float4 g_bnsc4[8], g_bnsh4[8];      // current-layer BN scale/shift
__device__ float  g_D[26 * 8 * 32 * 128];
__device__ float  g_G[(size_t)SEQL * 26 * 128];
__device__ float  g_tbias[128];
__device__ float  g_XJ[(size_t)NB * 256];
__device__ float  g_Z1[(size_t)NB * 1024];
__device__ float  g_Z2[(size_t)NB * 256];

// ---------------- helpers ----------------
__device__ __forceinline__ void red_add_v4(float* addr, float4 v) {
    asm volatile("red.global.add.v4.f32 [%0], {%1,%2,%3,%4};"
                 :: "l"(addr), "f"(v.x), "f"(v.y), "f"(v.z), "f"(v.w) : "memory");
}
__device__ __forceinline__ ull pack2(float a, float b) {
    ull r; asm("mov.b64 %0, {%1,%2};" : "=l"(r) : "f"(a), "f"(b)); return r;
}
__device__ __forceinline__ void unpack2(ull p, float& a, float& b) {
    asm("mov.b64 {%0,%1}, %2;" : "=f"(a), "=f"(b) : "l"(p));
}
__device__ __forceinline__ ull fma2(ull a, ull b, ull c) {
    ull d; asm("fma.rn.f32x2 %0, %1, %2, %3;" : "=l"(d) : "l"(a), "l"(b), "l"(c)); return d;
}
__device__ __forceinline__ ull add2(ull a, ull b) {
    ull d; asm("add.rn.f32x2 %0, %1, %2;" : "=l"(d) : "l"(a), "l"(b)); return d;
}
__device__ __forceinline__ ull relu2(ull p) {
    float a, b; unpack2(p, a, b);
    return pack2(fmaxf(a, 0.f), fmaxf(b, 0.f));
}

__global__ void init_kernel() {
    int t = threadIdx.x;
    for (int i = t; i < 64 * 64; i += 256) g_part[i] = 0.0;
    if (t < 32) {
        ((float*)g_bnsc4)[t] = 1.0f;
        ((float*)g_bnsh4)[t] = 0.0f;
    }
}

// ---------------- layer 1 projection: R = A = xd @ w1a ----------------
__global__ void __launch_bounds__(128) proj1_kernel(const float* __restrict__ xd,
                                                    const float* __restrict__ w1a) {
    __shared__ float ws[FXD * DIM];
    __shared__ float xs[128 * FXD];
    int tid = threadIdx.x;
    for (int i = tid; i < FXD * DIM; i += 128) ws[i] = w1a[i];
    size_t base = (size_t)blockIdx.x * 128 * FXD;
    for (int i = tid; i < 128 * FXD; i += 128) xs[i] = xd[base + i];
    __syncthreads();

    float y[DIM];
#pragma unroll
    for (int j = 0; j < DIM; j++) y[j] = 0.f;
    const float* ar = xs + tid * FXD;
    const float4* ws4 = reinterpret_cast<const float4*>(ws);
#pragma unroll 5
    for (int k = 0; k < FXD; k++) {
        float av = ar[k];
#pragma unroll
        for (int j4 = 0; j4 < 8; j4++) {
            float4 w = ws4[k * 8 + j4];
            y[j4*4+0] += av * w.x; y[j4*4+1] += av * w.y;
            y[j4*4+2] += av * w.z; y[j4*4+3] += av * w.w;
        }
    }
    size_t n = (size_t)blockIdx.x * 128 + tid;
    float4* ro = reinterpret_cast<float4*>(g_R + n * DIM);
    float4* ao = reinterpret_cast<float4*>(g_A + n * DIM);
#pragma unroll
    for (int j4 = 0; j4 < 8; j4++) {
        float4 v = make_float4(y[j4*4], y[j4*4+1], y[j4*4+2], y[j4*4+3]);
        ro[j4] = v; ao[j4] = v;
    }
}

// ---------------- edge scatter with on-the-fly BN: A[dst] += bn(R[src]) ----------------
__global__ void __launch_bounds__(256) edge_kernel(const int* __restrict__ ei) {
    int e = blockIdx.x * 256 + threadIdx.x;
    int s = ei[e];
    int d = ei[NE + e];
    const float4* xs = reinterpret_cast<const float4*>(g_R + (size_t)s * DIM);
    float* ad = g_A + (size_t)d * DIM;
#pragma unroll
    for (int j = 0; j < 8; j++) {
        float4 v  = __ldg(xs + j);
        float4 sc = g_bnsc4[j];
        float4 sh = g_bnsh4[j];
        v.x = fmaf(v.x, sc.x, sh.x);
        v.y = fmaf(v.y, sc.y, sh.y);
        v.z = fmaf(v.z, sc.z, sh.z);
        v.w = fmaf(v.w, sc.w, sh.w);
        red_add_v4(ad + j * 4, v);
    }
}

// ---------------- fused stats epilogue (shared transpose + staged double atomics) ----------------
__device__ __forceinline__ void stats_epilogue(float* sbuf, const float* v0, const float* v1,
                                               int t, int slot) {
#pragma unroll
    for (int j = 0; j < DIM; j++) sbuf[t * 36 + j] = v0[j] + v1[j];
    __syncthreads();
    if (t < 32) {
        float s = 0.f;
#pragma unroll 8
        for (int i = 0; i < 128; i++) s += sbuf[i * 36 + t];
        atomicAdd(&g_part[slot * 64 + t], (double)s);
    }
    __syncthreads();
#pragma unroll
    for (int j = 0; j < DIM; j++) sbuf[t * 36 + j] = v0[j] * v0[j] + v1[j] * v1[j];
    __syncthreads();
    if (t < 32) {
        float s = 0.f;
#pragma unroll 8
        for (int i = 0; i < 128; i++) s += sbuf[i * 36 + t];
        atomicAdd(&g_part[slot * 64 + 32 + t], (double)s);
    }
}

// ---------------- layer 1 second half: R = relu(relu(A+b1a)@w1b + b1b), + stats ----------------
__global__ void __launch_bounds__(128) mlp1b_kernel(const float* __restrict__ w1b,
                                                    const float* __restrict__ b1a,
                                                    const float* __restrict__ b1b) {
    __shared__ ull w2s[DIM * DIM];
    __shared__ ull bas[DIM], bbs[DIM];
    __shared__ float sbuf[128 * 36];
    int t = threadIdx.x;
    for (int i = t; i < DIM * DIM; i += 128) { float w = w1b[i]; w2s[i] = pack2(w, w); }
    if (t < DIM) { bas[t] = pack2(b1a[t], b1a[t]); bbs[t] = pack2(b1b[t], b1b[t]); }
    __syncthreads();

    size_t n0 = ((size_t)blockIdx.x * 128 + t) * 2;
    const float4* a0p = reinterpret_cast<const float4*>(g_A + n0 * DIM);
    const float4* a1p = reinterpret_cast<const float4*>(g_A + n0 * DIM + DIM);

    ull h[DIM];
#pragma unroll
    for (int q = 0; q < 8; q++) {
        float4 x0 = a0p[q], x1 = a1p[q];
        h[q*4+0] = relu2(add2(pack2(x0.x, x1.x), bas[q*4+0]));
        h[q*4+1] = relu2(add2(pack2(x0.y, x1.y), bas[q*4+1]));
        h[q*4+2] = relu2(add2(pack2(x0.z, x1.z), bas[q*4+2]));
        h[q*4+3] = relu2(add2(pack2(x0.w, x1.w), bas[q*4+3]));
    }
    ull r[DIM];
#pragma unroll
    for (int j = 0; j < DIM; j++) r[j] = bbs[j];
#pragma unroll
    for (int k = 0; k < DIM; k++) {
        const ulonglong2* wr2 = reinterpret_cast<const ulonglong2*>(&w2s[k * DIM]);
        ull hk = h[k];
#pragma unroll
        for (int j2 = 0; j2 < 16; j2++) {
            ulonglong2 w = wr2[j2];
            r[j2*2+0] = fma2(hk, w.x, r[j2*2+0]);
            r[j2*2+1] = fma2(hk, w.y, r[j2*2+1]);
        }
    }
    float v0[DIM], v1[DIM];
#pragma unroll
    for (int j = 0; j < DIM; j++) {
        float a, b; unpack2(r[j], a, b);
        v0[j] = fmaxf(a, 0.f); v1[j] = fmaxf(b, 0.f);
    }
    float4* ro = reinterpret_cast<float4*>(g_R + n0 * DIM);
#pragma unroll
    for (int q = 0; q < 8; q++) ro[q]     = make_float4(v0[q*4], v0[q*4+1], v0[q*4+2], v0[q*4+3]);
#pragma unroll
    for (int q = 0; q < 8; q++) ro[8 + q] = make_float4(v1[q*4], v1[q*4+1], v1[q*4+2], v1[q*4+3]);

    stats_epilogue(sbuf, v0, v1, t, blockIdx.x & 63);
}

// ---------------- layers 2-5 MLP: R = relu(relu(A@wa+ba)@wb+bb), + stats ----------------
__global__ void __launch_bounds__(128) mlp2_kernel(const float* __restrict__ wa,
                                                   const float* __restrict__ ba,
                                                   const float* __restrict__ wb,
                                                   const float* __restrict__ bb) {
    __shared__ ull w1s[DIM * DIM], w2s[DIM * DIM];
    __shared__ ull bas[DIM], bbs[DIM];
    __shared__ float sbuf[128 * 36];
    int t = threadIdx.x;
    for (int i = t; i < DIM * DIM; i += 128) {
        float w = wa[i]; w1s[i] = pack2(w, w);
        float v = wb[i]; w2s[i] = pack2(v, v);
    }
    if (t < DIM) { bas[t] = pack2(ba[t], ba[t]); bbs[t] = pack2(bb[t], bb[t]); }
    __syncthreads();

    size_t n0 = ((size_t)blockIdx.x * 128 + t) * 2;
    const float4* a0p = reinterpret_cast<const float4*>(g_A + n0 * DIM);
    const float4* a1p = reinterpret_cast<const float4*>(g_A + n0 * DIM + DIM);

    ull h[DIM];
#pragma unroll
    for (int j = 0; j < DIM; j++) h[j] = bas[j];
#pragma unroll
    for (int q = 0; q < 8; q++) {
        float4 x0 = a0p[q], x1 = a1p[q];
        ull a2[4] = { pack2(x0.x, x1.x), pack2(x0.y, x1.y),
                      pack2(x0.z, x1.z), pack2(x0.w, x1.w) };
#pragma unroll
        for (int kk = 0; kk < 4; kk++) {
            int k = q * 4 + kk;
            const ulonglong2* wr2 = reinterpret_cast<const ulonglong2*>(&w1s[k * DIM]);
            ull av = a2[kk];
#pragma unroll
            for (int j2 = 0; j2 < 16; j2++) {
                ulonglong2 w = wr2[j2];
                h[j2*2+0] = fma2(av, w.x, h[j2*2+0]);
                h[j2*2+1] = fma2(av, w.y, h[j2*2+1]);
            }
        }
    }
#pragma unroll
    for (int j = 0; j < DIM; j++) h[j] = relu2(h[j]);

    ull r[DIM];
#pragma unroll
    for (int j = 0; j < DIM; j++) r[j] = bbs[j];
#pragma unroll
    for (int k = 0; k < DIM; k++) {
        const ulonglong2* wr2 = reinterpret_cast<const ulonglong2*>(&w2s[k * DIM]);
        ull hk = h[k];
#pragma unroll
        for (int j2 = 0; j2 < 16; j2++) {
            ulonglong2 w = wr2[j2];
            r[j2*2+0] = fma2(hk, w.x, r[j2*2+0]);
            r[j2*2+1] = fma2(hk, w.y, r[j2*2+1]);
        }
    }
    float v0[DIM], v1[DIM];
#pragma unroll
    for (int j = 0; j < DIM; j++) {
        float a, b; unpack2(r[j], a, b);
        v0[j] = fmaxf(a, 0.f); v1[j] = fmaxf(b, 0.f);
    }
    float4* ro = reinterpret_cast<float4*>(g_R + n0 * DIM);
#pragma unroll
    for (int q = 0; q < 8; q++) ro[q]     = make_float4(v0[q*4], v0[q*4+1], v0[q*4+2], v0[q*4+3]);
#pragma unroll
    for (int q = 0; q < 8; q++) ro[8 + q] = make_float4(v1[q*4], v1[q*4+1], v1[q*4+2], v1[q*4+3]);

    stats_epilogue(sbuf, v0, v1, t, blockIdx.x & 63);
}

// ---------------- BN prep: reduce staged stats, compute scale/shift, zero slots ----------------
__global__ void bn_prep_kernel(const float* __restrict__ gamma,
                               const float* __restrict__ beta) {
    int c = threadIdx.x;
    if (c < DIM) {
        double s = 0.0, q = 0.0;
        for (int sl = 0; sl < 64; sl++) {
            s += g_part[sl * 64 + c];
            q += g_part[sl * 64 + 32 + c];
            g_part[sl * 64 + c] = 0.0;
            g_part[sl * 64 + 32 + c] = 0.0;
        }
        double inv = 1.0 / (double)NN;
        double mu  = s * inv;
        double var = q * inv - mu * mu;
        double sc  = (double)gamma[c] * rsqrt(var + 1e-5);
        ((float*)g_bnsc4)[c] = (float)sc;
        ((float*)g_bnsh4)[c] = (float)((double)beta[c] - mu * sc);
    }
}

// ---------------- A = bn(R)  (self term for next aggregation) ----------------
__global__ void __launch_bounds__(256) selfinit_kernel() {
    int i = blockIdx.x * 256 + threadIdx.x;   // float4 index
    float4 v = reinterpret_cast<const float4*>(g_R)[i];
    int q = i & 7;
    float4 sc = g_bnsc4[q], sh = g_bnsh4[q];
    v.x = fmaf(v.x, sc.x, sh.x);
    v.y = fmaf(v.y, sc.y, sh.y);
    v.z = fmaf(v.z, sc.z, sh.z);
    v.w = fmaf(v.w, sc.w, sh.w);
    reinterpret_cast<float4*>(g_A)[i] = v;
}

// ---------------- pooling (applies layer-5 BN) + fc1_xd -> XJ[:,0:128] ----------------
__global__ void __launch_bounds__(128) pool_fcd_kernel(const int* __restrict__ batch,
                                                       const float* __restrict__ fcd_w,
                                                       const float* __restrict__ fcd_b) {
    int b = blockIdx.x, tid = threadIdx.x;
    int lo, hi;
    { int key = b;     int l = 0,  h = NN; while (l < h) { int m = (l+h)>>1; if (batch[m] < key) l = m+1; else h = m; } lo = l; }
    { int key = b + 1; int l = lo, h = NN; while (l < h) { int m = (l+h)>>1; if (batch[m] < key) l = m+1; else h = m; } hi = l; }
    int cnt = hi - lo;
    int c = tid & 31, g = tid >> 5;
    float acc = 0.f;
    for (int r = lo + g; r < hi; r += 4) acc += g_R[(size_t)r * DIM + c];
    __shared__ float red[4][DIM];
    __shared__ float pooled[DIM];
    red[g][c] = acc;
    __syncthreads();
    if (tid < DIM) {
        float s = red[0][tid] + red[1][tid] + red[2][tid] + red[3][tid];
        float avg = s / fmaxf((float)cnt, 1.f);
        pooled[tid] = fmaf(avg, ((const float*)g_bnsc4)[tid], ((const float*)g_bnsh4)[tid]);
    }
    __syncthreads();
    float acc2 = fcd_b[tid];
#pragma unroll
    for (int k = 0; k < DIM; k++) acc2 += pooled[k] * fcd_w[k * OUTD + tid];
    g_XJ[(size_t)b * 256 + tid] = fmaxf(acc2, 0.f);
}

// ---------------- protein branch (folded linear) ----------------
__global__ void __launch_bounds__(128) d_kernel(const float* __restrict__ emb,
                                                const float* __restrict__ fct_w) {
    int bid = blockIdx.x;             // t*256 + k*32 + o
    int t = bid >> 8, k = (bid >> 5) & 7, o = bid & 31;
    __shared__ float es[EMBD];
    int tid = threadIdx.x;
    es[tid] = emb[t * EMBD + tid];
    __syncthreads();
    float acc = 0.f;
#pragma unroll 11
    for (int p = 0; p < LCONV; p++)
        acc += es[p + k] * fct_w[(size_t)(o * LCONV + p) * 128 + tid];
    g_D[((size_t)(t * 8 + k) * 32 + o) * 128 + tid] = acc;
}

__global__ void __launch_bounds__(128) g_kernel(const float* __restrict__ conv_w) {
    int c0 = blockIdx.x * 8, t = blockIdx.y, tid = threadIdx.x;
    __shared__ float ws[8][256];
    for (int i = tid; i < 8 * 256; i += 128) {
        int ci = i >> 8, m = i & 255, o = m >> 3, k = m & 7;
        ws[ci][m] = conv_w[(size_t)o * (SEQL * KW) + (size_t)(c0 + ci) * KW + k];
    }
    __syncthreads();
    float acc[8] = {0,0,0,0,0,0,0,0};
    for (int k = 0; k < 8; k++) {
#pragma unroll
        for (int o = 0; o < 32; o++) {
            float d = g_D[((size_t)(t * 8 + k) * 32 + o) * 128 + tid];
            int m = o * 8 + k;
#pragma unroll
            for (int ci = 0; ci < 8; ci++) acc[ci] += ws[ci][m] * d;
        }
    }
#pragma unroll
    for (int ci = 0; ci < 8; ci++)
        g_G[((size_t)(c0 + ci) * 26 + t) * 128 + tid] = acc[ci];
}

__global__ void __launch_bounds__(128) tbias_kernel(const float* __restrict__ conv_b,
                                                    const float* __restrict__ fct_w,
                                                    const float* __restrict__ fct_b) {
    int j = threadIdx.x;
    float acc = fct_b[j];
    for (int o = 0; o < NFLT; o++) {
        float cb = conv_b[o];
        for (int p = 0; p < LCONV; p++)
            acc += cb * fct_w[(size_t)(o * LCONV + p) * 128 + j];
    }
    g_tbias[j] = acc;
}

__global__ void __launch_bounds__(128) xtv_kernel(const int* __restrict__ xt) {
    int b = blockIdx.x, tid = threadIdx.x;
    __shared__ int ts[SEQL];
    for (int i = tid; i < SEQL; i += 128) ts[i] = xt[(size_t)b * SEQL + i];
    __syncthreads();
    float acc = g_tbias[tid];
#pragma unroll 4
    for (int c = 0; c < SEQL; c++)
        acc += g_G[((size_t)c * 26 + ts[c]) * 128 + tid];
    g_XJ[(size_t)b * 256 + 128 + tid] = acc;
}

// ---------------- classifier GEMMs ----------------
template <int STAGE>
__global__ void __launch_bounds__(256) gemm_relu_kernel(const float* __restrict__ W,
                                                        const float* __restrict__ bias) {
    const float* A = (STAGE == 0) ? g_XJ : g_Z1;
    float*       C = (STAGE == 0) ? g_Z1 : g_Z2;
    const int K  = (STAGE == 0) ? 256 : 1024;
    const int Nc = (STAGE == 0) ? 1024 : 256;

    __shared__ float As[16][68];
    __shared__ float Ws[16][68];
    int tid = threadIdx.x;
    int bm0 = blockIdx.y * 64, bn0 = blockIdx.x * 64;
    int tx = tid & 15, ty = tid >> 4;
    float acc[4][4] = {};
    int mL = tid >> 2, kqL = (tid & 3) * 4;
    int kkL = tid >> 4, nnL = (tid & 15) * 4;

    for (int k0 = 0; k0 < K; k0 += 16) {
        float4 a4 = *reinterpret_cast<const float4*>(A + (size_t)(bm0 + mL) * K + k0 + kqL);
        As[kqL+0][mL] = a4.x; As[kqL+1][mL] = a4.y;
        As[kqL+2][mL] = a4.z; As[kqL+3][mL] = a4.w;
        float4 w4 = *reinterpret_cast<const float4*>(W + (size_t)(k0 + kkL) * Nc + bn0 + nnL);
        *reinterpret_cast<float4*>(&Ws[kkL][nnL]) = w4;
        __syncthreads();
#pragma unroll
        for (int k = 0; k < 16; k++) {
            float4 av = *reinterpret_cast<const float4*>(&As[k][ty * 4]);
            float4 wv = *reinterpret_cast<const float4*>(&Ws[k][tx * 4]);
            acc[0][0] += av.x * wv.x; acc[0][1] += av.x * wv.y; acc[0][2] += av.x * wv.z; acc[0][3] += av.x * wv.w;
            acc[1][0] += av.y * wv.x; acc[1][1] += av.y * wv.y; acc[1][2] += av.y * wv.z; acc[1][3] += av.y * wv.w;
            acc[2][0] += av.z * wv.x; acc[2][1] += av.z * wv.y; acc[2][2] += av.z * wv.z; acc[2][3] += av.z * wv.w;
            acc[3][0] += av.w * wv.x; acc[3][1] += av.w * wv.y; acc[3][2] += av.w * wv.z; acc[3][3] += av.w * wv.w;
        }
        __syncthreads();
    }
    int nb = bn0 + tx * 4;
    float b0 = bias[nb], b1 = bias[nb+1], b2 = bias[nb+2], b3 = bias[nb+3];
#pragma unroll
    for (int i = 0; i < 4; i++) {
        int r = bm0 + ty * 4 + i;
        float4 v;
        v.x = fmaxf(acc[i][0] + b0, 0.f);
        v.y = fmaxf(acc[i][1] + b1, 0.f);
        v.z = fmaxf(acc[i][2] + b2, 0.f);
        v.w = fmaxf(acc[i][3] + b3, 0.f);
        *reinterpret_cast<float4*>(C + (size_t)r * Nc + nb) = v;
    }
}

__global__ void __launch_bounds__(256) final_kernel(const float* __restrict__ c3w,
                                                    const float* __restrict__ c3b,
                                                    float* __restrict__ out) {
    int gw = (blockIdx.x * blockDim.x + threadIdx.x) >> 5;
    int lane = threadIdx.x & 31;
    if (gw >= NB) return;
    float s = 0.f;
#pragma unroll
    for (int k = lane; k < 256; k += 32) s += g_Z2[(size_t)gw * 256 + k] * c3w[k];
#pragma unroll
    for (int o = 16; o > 0; o >>= 1) s += __shfl_down_sync(0xffffffffu, s, o);
    if (lane == 0) out[gw] = s + c3b[0];
}

// ---------------- launch ----------------
extern "C" void kernel_launch(void* const* d_in, const int* in_sizes, int n_in,
                              void* d_out, int out_size) {
    const float* xd = (const float*)d_in[0];
    const int*   ei = (const int*)d_in[1];
    const int*   xb = (const int*)d_in[2];
    const int*   xt = (const int*)d_in[3];
    const float* w1a = (const float*)d_in[4];
    const float* b1a = (const float*)d_in[5];
    const float* w1b = (const float*)d_in[6];
    const float* b1b = (const float*)d_in[7];
    const float* wa  = (const float*)d_in[8];
    const float* ba  = (const float*)d_in[9];
    const float* wb  = (const float*)d_in[10];
    const float* bb  = (const float*)d_in[11];
    const float* bng = (const float*)d_in[12];
    const float* bnb = (const float*)d_in[13];
    const float* fcd_w = (const float*)d_in[14];
    const float* fcd_b = (const float*)d_in[15];
    const float* emb   = (const float*)d_in[16];
    const float* conv_w = (const float*)d_in[17];
    const float* conv_b = (const float*)d_in[18];
    const float* fct_w  = (const float*)d_in[19];
    const float* fct_b  = (const float*)d_in[20];
    const float* c1w = (const float*)d_in[21];
    const float* c1b = (const float*)d_in[22];
    const float* c2w = (const float*)d_in[23];
    const float* c2b = (const float*)d_in[24];
    const float* c3w = (const float*)d_in[25];
    const float* c3b = (const float*)d_in[26];
    float* out = (float*)d_out;

    init_kernel<<<1, 256>>>();

    // ---- layer 1 ----
    proj1_kernel<<<NN / 128, 128>>>(xd, w1a);
    edge_kernel<<<NE / 256, 256>>>(ei);            // scale=1, shift=0
    mlp1b_kernel<<<NN / 256, 128>>>(w1b, b1a, b1b);

    // ---- layers 2-5 ----
    for (int i = 0; i < 4; i++) {
        bn_prep_kernel<<<1, 32>>>(bng + i * 32, bnb + i * 32);
        selfinit_kernel<<<NN * 8 / 256, 256>>>();
        edge_kernel<<<NE / 256, 256>>>(ei);
        mlp2_kernel<<<NN / 256, 128>>>(wa + i * 1024, ba + i * 32, wb + i * 1024, bb + i * 32);
    }
    bn_prep_kernel<<<1, 32>>>(bng + 4 * 32, bnb + 4 * 32);

    // ---- pooling + fc1_xd ----
    pool_fcd_kernel<<<NB, 128>>>(xb, fcd_w, fcd_b);

    // ---- protein branch ----
    d_kernel<<<26 * 256, 128>>>(emb, fct_w);
    {
        dim3 g(SEQL / 8, 26);
        g_kernel<<<g, 128>>>(conv_w);
    }
    tbias_kernel<<<1, 128>>>(conv_b, fct_w, fct_b);
    xtv_kernel<<<NB, 128>>>(xt);

    // ---- classifier ----
    {
        dim3 g1(1024 / 64, NB / 64);
        gemm_relu_kernel<0><<<g1, 256>>>(c1w, c1b);
        dim3 g2(256 / 64, NB / 64);
        gemm_relu_kernel<1><<<g2, 256>>>(c2w, c2b);
    }
    final_kernel<<<NB / 8, 256>>>(c3w, c3b, out);
}

// round 6
// speedup vs baseline: 1.3954x; 1.3954x over previous
#include <cuda_runtime.h>
#include <cstdint>

#define NN   1048576
#define NE   4194304
#define NB   2048
#define DIM  32
#define FXD  55
#define OUTD 128
#define SEQL 1000
#define EMBD 128
#define NFLT 32
#define KW   8
#define LCONV 121

// ---------------- device scratch ----------------
__device__ float  g_A[(size_t)NN * DIM];     // aggregated (BN-applied) features
__device__ float  g_R[(size_t)NN * DIM];     // post-relu pre-BN features
__device__ double g_stats[5 * 64];           // per-layer [sum(32) | sumsq(32)]
__device__ float  g_bnscale[DIM], g_bnshift[DIM];  // current-layer BN
__device__ int    g_deg[NN];
__device__ int    g_ptr[NN + 1];
__device__ int    g_cursor[NN];
__device__ int    g_srcs[NE];
__device__ int    g_bsum[1024], g_boff[1024];
__device__ float  g_D[26 * 8 * 32 * 128];
__device__ float  g_G[(size_t)SEQL * 26 * 128];
__device__ float  g_tbias[128];
__device__ float  g_XJ[(size_t)NB * 256];
__device__ float  g_Z1[(size_t)NB * 1024];
__device__ float  g_Z2[(size_t)NB * 256];

// ---------------- init: zero stats, identity BN ----------------
__global__ void init_kernel() {
    int i = threadIdx.x;
    if (i < 5 * 64) g_stats[i] = 0.0;
    if (i < DIM) { g_bnscale[i] = 1.0f; g_bnshift[i] = 0.0f; }
}

// ---------------- CSR build ----------------
__global__ void __launch_bounds__(256) zero_deg_kernel() {
    int i = blockIdx.x * 256 + threadIdx.x;           // int4 index, NN/4 total
    reinterpret_cast<int4*>(g_deg)[i] = make_int4(0, 0, 0, 0);
}

__global__ void __launch_bounds__(256) hist_kernel(const int* __restrict__ ei) {
    int e = blockIdx.x * 256 + threadIdx.x;
    atomicAdd(&g_deg[ei[NE + e]], 1);
}

__global__ void __launch_bounds__(256) scan1_kernel() {
    int b = blockIdx.x, t = threadIdx.x;
    int4 v = reinterpret_cast<const int4*>(g_deg)[b * 256 + t];
    int s = v.x + v.y + v.z + v.w;
#pragma unroll
    for (int o = 16; o; o >>= 1) s += __shfl_down_sync(0xffffffffu, s, o);
    __shared__ int ws[8];
    if ((t & 31) == 0) ws[t >> 5] = s;
    __syncthreads();
    if (t == 0) {
        int tot = 0;
#pragma unroll
        for (int i = 0; i < 8; i++) tot += ws[i];
        g_bsum[b] = tot;
    }
}

__global__ void __launch_bounds__(1024) scan2_kernel() {
    __shared__ int s[1024];
    int t = threadIdx.x;
    int my = g_bsum[t];
    s[t] = my;
    __syncthreads();
    for (int off = 1; off < 1024; off <<= 1) {
        int v = (t >= off) ? s[t - off] : 0;
        __syncthreads();
        s[t] += v;
        __syncthreads();
    }
    g_boff[t] = s[t] - my;   // exclusive
}

__global__ void __launch_bounds__(256) scan3_kernel() {
    int b = blockIdx.x, t = threadIdx.x;
    int4 v = reinterpret_cast<const int4*>(g_deg)[b * 256 + t];
    int l1 = v.x, l2 = v.x + v.y, l3 = v.x + v.y + v.z;
    int tsum = l3 + v.w;
    __shared__ int s[256];
    s[t] = tsum;
    __syncthreads();
    for (int off = 1; off < 256; off <<= 1) {
        int x = (t >= off) ? s[t - off] : 0;
        __syncthreads();
        s[t] += x;
        __syncthreads();
    }
    int base = g_boff[b] + s[t] - tsum;
    int i0 = b * 1024 + t * 4;
    g_ptr[i0]     = base;      g_cursor[i0]     = base;
    g_ptr[i0 + 1] = base + l1; g_cursor[i0 + 1] = base + l1;
    g_ptr[i0 + 2] = base + l2; g_cursor[i0 + 2] = base + l2;
    g_ptr[i0 + 3] = base + l3; g_cursor[i0 + 3] = base + l3;
    if (b == 1023 && t == 255) g_ptr[NN] = NE;
}

__global__ void __launch_bounds__(256) fill_kernel(const int* __restrict__ ei) {
    int e = blockIdx.x * 256 + threadIdx.x;
    int s = ei[e];
    int d = ei[NE + e];
    int pos = atomicAdd(&g_cursor[d], 1);
    g_srcs[pos] = s;
}

// ---------------- layer 1 projection: R = xd @ w1a ----------------
__global__ void __launch_bounds__(128) proj1_kernel(const float* __restrict__ xd,
                                                    const float* __restrict__ w1a) {
    __shared__ float ws[FXD * DIM];
    __shared__ float xs[128 * FXD];
    int tid = threadIdx.x;
    for (int i = tid; i < FXD * DIM; i += 128) ws[i] = w1a[i];
    size_t base = (size_t)blockIdx.x * 128 * FXD;
    for (int i = tid; i < 128 * FXD; i += 128) xs[i] = xd[base + i];
    __syncthreads();

    float y[DIM];
#pragma unroll
    for (int j = 0; j < DIM; j++) y[j] = 0.f;
    const float* ar = xs + tid * FXD;
    const float4* ws4 = reinterpret_cast<const float4*>(ws);
#pragma unroll 5
    for (int k = 0; k < FXD; k++) {
        float av = ar[k];
#pragma unroll
        for (int j4 = 0; j4 < 8; j4++) {
            float4 w = ws4[k * 8 + j4];
            y[j4*4+0] += av * w.x; y[j4*4+1] += av * w.y;
            y[j4*4+2] += av * w.z; y[j4*4+3] += av * w.w;
        }
    }
    size_t n = (size_t)blockIdx.x * 128 + tid;
    float4* ro = reinterpret_cast<float4*>(g_R + n * DIM);
#pragma unroll
    for (int j4 = 0; j4 < 8; j4++)
        ro[j4] = make_float4(y[j4*4], y[j4*4+1], y[j4*4+2], y[j4*4+3]);
}

// ---------------- CSR aggregation: A[n] = sc*(R[n] + sum R[src]) + cnt*sh ----------------
__global__ void __launch_bounds__(256) agg_kernel() {
    int tid = threadIdx.x;
    int node = blockIdx.x * 32 + (tid >> 3);   // 8 threads per node
    int sub = tid & 7;                          // float4 lane
    const float4* R4 = reinterpret_cast<const float4*>(g_R);
    float4 sc = reinterpret_cast<const float4*>(g_bnscale)[sub];
    float4 sh = reinterpret_cast<const float4*>(g_bnshift)[sub];
    int base = g_ptr[node], end = g_ptr[node + 1];
    float4 s = __ldg(R4 + (size_t)node * 8 + sub);
    float cnt = 1.f;
    for (int i = base; i < end; i++) {
        int src = __ldg(&g_srcs[i]);
        float4 v = __ldg(R4 + (size_t)src * 8 + sub);
        s.x += v.x; s.y += v.y; s.z += v.z; s.w += v.w;
        cnt += 1.f;
    }
    float4 o;
    o.x = fmaf(s.x, sc.x, cnt * sh.x);
    o.y = fmaf(s.y, sc.y, cnt * sh.y);
    o.z = fmaf(s.z, sc.z, cnt * sh.z);
    o.w = fmaf(s.w, sc.w, cnt * sh.w);
    reinterpret_cast<float4*>(g_A)[(size_t)node * 8 + sub] = o;
}

// ---------------- layer 1 second half: R = relu(relu(A + b1a) @ w1b + b1b) ----------------
__global__ void __launch_bounds__(128) mlp1b_kernel(const float* __restrict__ w1b,
                                                    const float* __restrict__ b1a,
                                                    const float* __restrict__ b1b) {
    __shared__ float wbs[DIM * DIM], bas[DIM], bbs[DIM];
    int tid = threadIdx.x;
    for (int i = tid; i < DIM * DIM; i += 128) wbs[i] = w1b[i];
    if (tid < DIM) { bas[tid] = b1a[tid]; bbs[tid] = b1b[tid]; }
    __syncthreads();

    size_t n = (size_t)blockIdx.x * 128 + tid;
    float h[DIM];
    const float4* ar = reinterpret_cast<const float4*>(g_A + n * DIM);
#pragma unroll
    for (int q = 0; q < 8; q++) {
        float4 v = ar[q];
        h[q*4]   = fmaxf(v.x + bas[q*4],   0.f);
        h[q*4+1] = fmaxf(v.y + bas[q*4+1], 0.f);
        h[q*4+2] = fmaxf(v.z + bas[q*4+2], 0.f);
        h[q*4+3] = fmaxf(v.w + bas[q*4+3], 0.f);
    }
    float r[DIM];
#pragma unroll
    for (int j = 0; j < DIM; j++) r[j] = bbs[j];
    const float4* wb4 = reinterpret_cast<const float4*>(wbs);
#pragma unroll
    for (int k = 0; k < DIM; k++) {
        float av = h[k];
#pragma unroll
        for (int j4 = 0; j4 < 8; j4++) {
            float4 w = wb4[k * 8 + j4];
            r[j4*4+0] += av * w.x; r[j4*4+1] += av * w.y;
            r[j4*4+2] += av * w.z; r[j4*4+3] += av * w.w;
        }
    }
    float4* ro = reinterpret_cast<float4*>(g_R + n * DIM);
#pragma unroll
    for (int j4 = 0; j4 < 8; j4++)
        ro[j4] = make_float4(fmaxf(r[j4*4],0.f), fmaxf(r[j4*4+1],0.f),
                             fmaxf(r[j4*4+2],0.f), fmaxf(r[j4*4+3],0.f));
}

// ---------------- layers 2-5 MLP ----------------
__global__ void __launch_bounds__(128) mlp2_kernel(const float* __restrict__ wa,
                                                   const float* __restrict__ ba,
                                                   const float* __restrict__ wb,
                                                   const float* __restrict__ bb) {
    __shared__ float was[DIM * DIM], wbs[DIM * DIM], bas[DIM], bbs[DIM];
    int tid = threadIdx.x;
    for (int i = tid; i < DIM * DIM; i += 128) { was[i] = wa[i]; wbs[i] = wb[i]; }
    if (tid < DIM) { bas[tid] = ba[tid]; bbs[tid] = bb[tid]; }
    __syncthreads();

    size_t n = (size_t)blockIdx.x * 128 + tid;
    float a[DIM];
    const float4* ar = reinterpret_cast<const float4*>(g_A + n * DIM);
#pragma unroll
    for (int q = 0; q < 8; q++) {
        float4 v = ar[q];
        a[q*4] = v.x; a[q*4+1] = v.y; a[q*4+2] = v.z; a[q*4+3] = v.w;
    }
    float h[DIM];
#pragma unroll
    for (int j = 0; j < DIM; j++) h[j] = bas[j];
    const float4* wa4 = reinterpret_cast<const float4*>(was);
#pragma unroll
    for (int k = 0; k < DIM; k++) {
        float av = a[k];
#pragma unroll
        for (int j4 = 0; j4 < 8; j4++) {
            float4 w = wa4[k * 8 + j4];
            h[j4*4+0] += av * w.x; h[j4*4+1] += av * w.y;
            h[j4*4+2] += av * w.z; h[j4*4+3] += av * w.w;
        }
    }
#pragma unroll
    for (int j = 0; j < DIM; j++) h[j] = fmaxf(h[j], 0.f);

    float r[DIM];
#pragma unroll
    for (int j = 0; j < DIM; j++) r[j] = bbs[j];
    const float4* wb4 = reinterpret_cast<const float4*>(wbs);
#pragma unroll
    for (int k = 0; k < DIM; k++) {
        float av = h[k];
#pragma unroll
        for (int j4 = 0; j4 < 8; j4++) {
            float4 w = wb4[k * 8 + j4];
            r[j4*4+0] += av * w.x; r[j4*4+1] += av * w.y;
            r[j4*4+2] += av * w.z; r[j4*4+3] += av * w.w;
        }
    }
    float4* ro = reinterpret_cast<float4*>(g_R + n * DIM);
#pragma unroll
    for (int j4 = 0; j4 < 8; j4++)
        ro[j4] = make_float4(fmaxf(r[j4*4],0.f), fmaxf(r[j4*4+1],0.f),
                             fmaxf(r[j4*4+2],0.f), fmaxf(r[j4*4+3],0.f));
}

// ---------------- BN stats: per-channel sum/sumsq in double ----------------
__global__ void __launch_bounds__(256) stats_kernel(int layer) {
    int tid = threadIdx.x;
    int lane = tid & 31;
    int gw = blockIdx.x * (blockDim.x >> 5) + (tid >> 5);
    int nw = gridDim.x * (blockDim.x >> 5);
    double s = 0.0, q = 0.0;
    for (int r = gw; r < NN; r += nw) {
        double v = (double)g_R[(size_t)r * DIM + lane];
        s += v; q += v * v;
    }
    __shared__ double ss[DIM], sq[DIM];
    if (tid < DIM) { ss[tid] = 0.0; sq[tid] = 0.0; }
    __syncthreads();
    atomicAdd(&ss[lane], s);
    atomicAdd(&sq[lane], q);
    __syncthreads();
    if (tid < DIM) {
        atomicAdd(&g_stats[layer * 64 + tid], ss[tid]);
        atomicAdd(&g_stats[layer * 64 + 32 + tid], sq[tid]);
    }
}

__global__ void bn_prep_kernel(const float* __restrict__ gamma,
                               const float* __restrict__ beta, int layer) {
    int c = threadIdx.x;
    if (c < DIM) {
        double inv = 1.0 / (double)NN;
        double mu  = g_stats[layer * 64 + c] * inv;
        double var = g_stats[layer * 64 + 32 + c] * inv - mu * mu;
        double sc  = (double)gamma[c] * rsqrt(var + 1e-5);
        g_bnscale[c] = (float)sc;
        g_bnshift[c] = (float)((double)beta[c] - mu * sc);
    }
}

// ---------------- pooling (applies layer-5 BN on pooled) + fc1_xd ----------------
__global__ void __launch_bounds__(128) pool_fcd_kernel(const int* __restrict__ batch,
                                                       const float* __restrict__ fcd_w,
                                                       const float* __restrict__ fcd_b) {
    int b = blockIdx.x, tid = threadIdx.x;
    int lo, hi;
    { int key = b;     int l = 0,  h = NN; while (l < h) { int m = (l+h)>>1; if (batch[m] < key) l = m+1; else h = m; } lo = l; }
    { int key = b + 1; int l = lo, h = NN; while (l < h) { int m = (l+h)>>1; if (batch[m] < key) l = m+1; else h = m; } hi = l; }
    int cnt = hi - lo;
    int c = tid & 31, g = tid >> 5;
    float acc = 0.f;
    for (int r = lo + g; r < hi; r += 4) acc += g_R[(size_t)r * DIM + c];
    __shared__ float red[4][DIM];
    __shared__ float pooled[DIM];
    red[g][c] = acc;
    __syncthreads();
    if (tid < DIM) {
        float s = red[0][tid] + red[1][tid] + red[2][tid] + red[3][tid];
        float avg = s / fmaxf((float)cnt, 1.f);
        pooled[tid] = fmaf(avg, g_bnscale[tid], g_bnshift[tid]);
    }
    __syncthreads();
    float acc2 = fcd_b[tid];
#pragma unroll
    for (int k = 0; k < DIM; k++) acc2 += pooled[k] * fcd_w[k * OUTD + tid];
    g_XJ[(size_t)b * 256 + tid] = fmaxf(acc2, 0.f);
}

// ---------------- protein branch ----------------
__global__ void __launch_bounds__(128) d_kernel(const float* __restrict__ emb,
                                                const float* __restrict__ fct_w) {
    int bid = blockIdx.x;             // t*256 + k*32 + o
    int t = bid >> 8, k = (bid >> 5) & 7, o = bid & 31;
    __shared__ float es[EMBD];
    int tid = threadIdx.x;
    es[tid] = emb[t * EMBD + tid];
    __syncthreads();
    float acc = 0.f;
#pragma unroll 11
    for (int p = 0; p < LCONV; p++)
        acc += es[p + k] * fct_w[(size_t)(o * LCONV + p) * 128 + tid];
    g_D[((size_t)(t * 8 + k) * 32 + o) * 128 + tid] = acc;
}

__global__ void __launch_bounds__(128) g_kernel(const float* __restrict__ conv_w) {
    int c0 = blockIdx.x * 8, t = blockIdx.y, tid = threadIdx.x;
    __shared__ float ws[8][256];
    for (int i = tid; i < 8 * 256; i += 128) {
        int ci = i >> 8, m = i & 255, o = m >> 3, k = m & 7;
        ws[ci][m] = conv_w[(size_t)o * (SEQL * KW) + (size_t)(c0 + ci) * KW + k];
    }
    __syncthreads();
    float acc[8] = {0,0,0,0,0,0,0,0};
    for (int k = 0; k < 8; k++) {
#pragma unroll
        for (int o = 0; o < 32; o++) {
            float d = g_D[((size_t)(t * 8 + k) * 32 + o) * 128 + tid];
            int m = o * 8 + k;
#pragma unroll
            for (int ci = 0; ci < 8; ci++) acc[ci] += ws[ci][m] * d;
        }
    }
#pragma unroll
    for (int ci = 0; ci < 8; ci++)
        g_G[((size_t)(c0 + ci) * 26 + t) * 128 + tid] = acc[ci];
}

__global__ void __launch_bounds__(128) tbias_kernel(const float* __restrict__ conv_b,
                                                    const float* __restrict__ fct_w,
                                                    const float* __restrict__ fct_b) {
    int j = threadIdx.x;
    float acc = fct_b[j];
    for (int o = 0; o < NFLT; o++) {
        float cb = conv_b[o];
        for (int p = 0; p < LCONV; p++)
            acc += cb * fct_w[(size_t)(o * LCONV + p) * 128 + j];
    }
    g_tbias[j] = acc;
}

__global__ void __launch_bounds__(128) xtv_kernel(const int* __restrict__ xt) {
    int b = blockIdx.x, tid = threadIdx.x;
    __shared__ int ts[SEQL];
    for (int i = tid; i < SEQL; i += 128) ts[i] = xt[(size_t)b * SEQL + i];
    __syncthreads();
    float acc = g_tbias[tid];
#pragma unroll 4
    for (int c = 0; c < SEQL; c++)
        acc += g_G[((size_t)c * 26 + ts[c]) * 128 + tid];
    g_XJ[(size_t)b * 256 + 128 + tid] = acc;
}

// ---------------- classifier GEMMs ----------------
template <int STAGE>
__global__ void __launch_bounds__(256) gemm_relu_kernel(const float* __restrict__ W,
                                                        const float* __restrict__ bias) {
    const float* A = (STAGE == 0) ? g_XJ : g_Z1;
    float*       C = (STAGE == 0) ? g_Z1 : g_Z2;
    const int K  = (STAGE == 0) ? 256 : 1024;
    const int Nc = (STAGE == 0) ? 1024 : 256;

    __shared__ float As[16][68];
    __shared__ float Ws[16][68];
    int tid = threadIdx.x;
    int bm0 = blockIdx.y * 64, bn0 = blockIdx.x * 64;
    int tx = tid & 15, ty = tid >> 4;
    float acc[4][4] = {};
    int mL = tid >> 2, kqL = (tid & 3) * 4;
    int kkL = tid >> 4, nnL = (tid & 15) * 4;

    for (int k0 = 0; k0 < K; k0 += 16) {
        float4 a4 = *reinterpret_cast<const float4*>(A + (size_t)(bm0 + mL) * K + k0 + kqL);
        As[kqL+0][mL] = a4.x; As[kqL+1][mL] = a4.y;
        As[kqL+2][mL] = a4.z; As[kqL+3][mL] = a4.w;
        float4 w4 = *reinterpret_cast<const float4*>(W + (size_t)(k0 + kkL) * Nc + bn0 + nnL);
        *reinterpret_cast<float4*>(&Ws[kkL][nnL]) = w4;
        __syncthreads();
#pragma unroll
        for (int k = 0; k < 16; k++) {
            float4 av = *reinterpret_cast<const float4*>(&As[k][ty * 4]);
            float4 wv = *reinterpret_cast<const float4*>(&Ws[k][tx * 4]);
            acc[0][0] += av.x * wv.x; acc[0][1] += av.x * wv.y; acc[0][2] += av.x * wv.z; acc[0][3] += av.x * wv.w;
            acc[1][0] += av.y * wv.x; acc[1][1] += av.y * wv.y; acc[1][2] += av.y * wv.z; acc[1][3] += av.y * wv.w;
            acc[2][0] += av.z * wv.x; acc[2][1] += av.z * wv.y; acc[2][2] += av.z * wv.z; acc[2][3] += av.z * wv.w;
            acc[3][0] += av.w * wv.x; acc[3][1] += av.w * wv.y; acc[3][2] += av.w * wv.z; acc[3][3] += av.w * wv.w;
        }
        __syncthreads();
    }
    int nb = bn0 + tx * 4;
    float b0 = bias[nb], b1 = bias[nb+1], b2 = bias[nb+2], b3 = bias[nb+3];
#pragma unroll
    for (int i = 0; i < 4; i++) {
        int r = bm0 + ty * 4 + i;
        float4 v;
        v.x = fmaxf(acc[i][0] + b0, 0.f);
        v.y = fmaxf(acc[i][1] + b1, 0.f);
        v.z = fmaxf(acc[i][2] + b2, 0.f);
        v.w = fmaxf(acc[i][3] + b3, 0.f);
        *reinterpret_cast<float4*>(C + (size_t)r * Nc + nb) = v;
    }
}

__global__ void __launch_bounds__(256) final_kernel(const float* __restrict__ c3w,
                                                    const float* __restrict__ c3b,
                                                    float* __restrict__ out) {
    int gw = (blockIdx.x * blockDim.x + threadIdx.x) >> 5;
    int lane = threadIdx.x & 31;
    if (gw >= NB) return;
    float s = 0.f;
#pragma unroll
    for (int k = lane; k < 256; k += 32) s += g_Z2[(size_t)gw * 256 + k] * c3w[k];
#pragma unroll
    for (int o = 16; o > 0; o >>= 1) s += __shfl_down_sync(0xffffffffu, s, o);
    if (lane == 0) out[gw] = s + c3b[0];
}

// ---------------- launch ----------------
extern "C" void kernel_launch(void* const* d_in, const int* in_sizes, int n_in,
                              void* d_out, int out_size) {
    const float* xd = (const float*)d_in[0];
    const int*   ei = (const int*)d_in[1];
    const int*   xb = (const int*)d_in[2];
    const int*   xt = (const int*)d_in[3];
    const float* w1a = (const float*)d_in[4];
    const float* b1a = (const float*)d_in[5];
    const float* w1b = (const float*)d_in[6];
    const float* b1b = (const float*)d_in[7];
    const float* wa  = (const float*)d_in[8];
    const float* ba  = (const float*)d_in[9];
    const float* wb  = (const float*)d_in[10];
    const float* bb  = (const float*)d_in[11];
    const float* bng = (const float*)d_in[12];
    const float* bnb = (const float*)d_in[13];
    const float* fcd_w = (const float*)d_in[14];
    const float* fcd_b = (const float*)d_in[15];
    const float* emb   = (const float*)d_in[16];
    const float* conv_w = (const float*)d_in[17];
    const float* conv_b = (const float*)d_in[18];
    const float* fct_w  = (const float*)d_in[19];
    const float* fct_b  = (const float*)d_in[20];
    const float* c1w = (const float*)d_in[21];
    const float* c1b = (const float*)d_in[22];
    const float* c2w = (const float*)d_in[23];
    const float* c2b = (const float*)d_in[24];
    const float* c3w = (const float*)d_in[25];
    const float* c3b = (const float*)d_in[26];
    float* out = (float*)d_out;

    init_kernel<<<1, 320>>>();

    // ---- CSR build (dst-sorted adjacency) ----
    zero_deg_kernel<<<NN / 1024, 256>>>();
    hist_kernel<<<NE / 256, 256>>>(ei);
    scan1_kernel<<<1024, 256>>>();
    scan2_kernel<<<1, 1024>>>();
    scan3_kernel<<<1024, 256>>>();
    fill_kernel<<<NE / 256, 256>>>(ei);

    // ---- layer 1 (project first, aggregate in 32-dim space) ----
    proj1_kernel<<<NN / 128, 128>>>(xd, w1a);
    agg_kernel<<<NN / 32, 256>>>();                     // identity BN (init)
    mlp1b_kernel<<<NN / 128, 128>>>(w1b, b1a, b1b);
    stats_kernel<<<2048, 256>>>(0);
    bn_prep_kernel<<<1, 32>>>(bng, bnb, 0);

    // ---- layers 2-5 ----
    for (int i = 0; i < 4; i++) {
        agg_kernel<<<NN / 32, 256>>>();                 // applies layer-i BN on the fly
        mlp2_kernel<<<NN / 128, 128>>>(wa + i * 1024, ba + i * 32, wb + i * 1024, bb + i * 32);
        stats_kernel<<<2048, 256>>>(i + 1);
        bn_prep_kernel<<<1, 32>>>(bng + (i + 1) * 32, bnb + (i + 1) * 32, i + 1);
    }

    // ---- pooling + fc1_xd ----
    pool_fcd_kernel<<<NB, 128>>>(xb, fcd_w, fcd_b);

    // ---- protein branch (folded linear) ----
    d_kernel<<<26 * 256, 128>>>(emb, fct_w);
    {
        dim3 g(SEQL / 8, 26);
        g_kernel<<<g, 128>>>(conv_w);
    }
    tbias_kernel<<<1, 128>>>(conv_b, fct_w, fct_b);
    xtv_kernel<<<NB, 128>>>(xt);

    // ---- classifier ----
    {
        dim3 g1(1024 / 64, NB / 64);
        gemm_relu_kernel<0><<<g1, 256>>>(c1w, c1b);
        dim3 g2(256 / 64, NB / 64);
        gemm_relu_kernel<1><<<g2, 256>>>(c2w, c2b);
    }
    final_kernel<<<NB / 8, 256>>>(c3w, c3b, out);
}